// round 3
// baseline (speedup 1.0000x reference)
#include <cuda_runtime.h>
#include <math.h>

#define BB 32
#define SS 4096
#define HH 1024
#define NCHUNK 64
#define CHUNK (SS / NCHUNK)            // 64 rows per block
#define ROWS_PER_WARP (CHUNK / 8)      // 8 rows per warp
#define NEG_BIG -1.0e9f

// ---- scratch (no allocations allowed) ----
__device__ float g_q[BB * HH];                    // projected query
__device__ float g_part_m[BB * NCHUNK];           // per-chunk running max
__device__ float g_part_l[BB * NCHUNK];           // per-chunk exp-sum
__device__ float g_part_acc[BB * NCHUNK * HH];    // per-chunk unnormalized context (8MB)

// ============================================================
// Kernel A: q[b,o] = sum_h query[b,h] * W[o,h]
// grid (HH/8) = 128 blocks, 256 threads. Warp per output row o.
// W is read exactly ONCE (4MB). Queries (128KB) hit L2.
// ============================================================
__global__ void __launch_bounds__(256) proj_kernel(
    const float* __restrict__ query, const float* __restrict__ W)
{
    const int tid = threadIdx.x;
    const int w = tid >> 5, lane = tid & 31;
    const int o = blockIdx.x * 8 + w;

    // W row: 32 floats/lane as 8 x float4 (read once, kept in regs)
    const float4* wrow = (const float4*)(W + (size_t)o * HH);
    float4 wv[8];
    #pragma unroll
    for (int j = 0; j < 8; j++) wv[j] = wrow[j * 32 + lane];

    const float4* qbase = (const float4*)query;
    #pragma unroll 4
    for (int b = 0; b < BB; b++) {
        float p = 0.f;
        #pragma unroll
        for (int j = 0; j < 8; j++) {
            float4 qv = __ldg(qbase + (size_t)b * (HH / 4) + j * 32 + lane);
            p += wv[j].x * qv.x + wv[j].y * qv.y + wv[j].z * qv.z + wv[j].w * qv.w;
        }
        #pragma unroll
        for (int off = 16; off > 0; off >>= 1)
            p += __shfl_xor_sync(0xffffffffu, p, off);
        if (lane == 0) g_q[(size_t)b * HH + o] = p;
    }
}

// ============================================================
// Kernel B: fused scores + online softmax + context partial.
// grid (NCHUNK, B) = 2048 CTAs, 256 threads (8 warps), warp-per-row.
// q lives in smem (frees 32 regs -> higher occupancy).
// Keys streamed with __ldcs (zero reuse; don't churn L2).
// ============================================================
__global__ void __launch_bounds__(256) flash_kernel(
    const float* __restrict__ keys,
    const int* __restrict__ mask,
    float* __restrict__ scores_out)
{
    const int chunk = blockIdx.x, b = blockIdx.y;
    const int tid = threadIdx.x, w = tid >> 5, lane = tid & 31;

    __shared__ float4 sq[HH / 4];          // 4KB projected query
    __shared__ float  s_m[8], s_l[8];
    __shared__ float4 s_acc[8][256];       // 32KB warp partial contexts

    {
        const float4* qsrc = (const float4*)(g_q + (size_t)b * HH);
        for (int i = tid; i < HH / 4; i += 256) sq[i] = qsrc[i];
    }
    __syncthreads();

    float4 acc[8];
    #pragma unroll
    for (int j = 0; j < 8; j++) acc[j] = make_float4(0.f, 0.f, 0.f, 0.f);
    float m = -INFINITY, l = 0.f;

    const int s0 = chunk * CHUNK + w * ROWS_PER_WARP;
    const int* mrow = mask + (size_t)b * SS;

    #pragma unroll 2
    for (int r = 0; r < ROWS_PER_WARP; r++) {
        const int s = s0 + r;
        const float4* kp = (const float4*)(keys + ((size_t)b * SS + s) * HH);

        float4 kv[8];
        float p = 0.f;
        #pragma unroll
        for (int j = 0; j < 8; j++) {
            kv[j] = __ldcs(kp + j * 32 + lane);
            float4 qv = sq[j * 32 + lane];
            p += kv[j].x * qv.x + kv[j].y * qv.y +
                 kv[j].z * qv.z + kv[j].w * qv.w;
        }
        #pragma unroll
        for (int off = 16; off > 0; off >>= 1)
            p += __shfl_xor_sync(0xffffffffu, p, off);

        const float score = (mrow[s] != 0) ? NEG_BIG : p;
        if (lane == 0) scores_out[(size_t)b * SS + s] = score;

        // online softmax update; key row still in registers
        const float mn = fmaxf(m, score);
        const float c  = __expf(m - mn);      // exp(-inf)=0 on first iter
        const float e  = __expf(score - mn);
        l = l * c + e;
        #pragma unroll
        for (int j = 0; j < 8; j++) {
            acc[j].x = acc[j].x * c + e * kv[j].x;
            acc[j].y = acc[j].y * c + e * kv[j].y;
            acc[j].z = acc[j].z * c + e * kv[j].z;
            acc[j].w = acc[j].w * c + e * kv[j].w;
        }
        m = mn;
    }

    // ---- combine 8 warps within the block ----
    if (lane == 0) { s_m[w] = m; s_l[w] = l; }
    #pragma unroll
    for (int j = 0; j < 8; j++) s_acc[w][j * 32 + lane] = acc[j];
    __syncthreads();

    float M = s_m[0];
    #pragma unroll
    for (int i = 1; i < 8; i++) M = fmaxf(M, s_m[i]);
    float ew[8], L = 0.f;
    #pragma unroll
    for (int i = 0; i < 8; i++) { ew[i] = __expf(s_m[i] - M); L += ew[i] * s_l[i]; }

    float4 cacc = make_float4(0.f, 0.f, 0.f, 0.f);
    #pragma unroll
    for (int i = 0; i < 8; i++) {
        float4 v = s_acc[i][tid];
        cacc.x += ew[i] * v.x; cacc.y += ew[i] * v.y;
        cacc.z += ew[i] * v.z; cacc.w += ew[i] * v.w;
    }
    const int pidx = b * NCHUNK + chunk;
    ((float4*)(g_part_acc + (size_t)pidx * HH))[tid] = cacc;
    if (tid == 0) { g_part_m[pidx] = M; g_part_l[pidx] = L; }
}

// ============================================================
// Kernel C: combine chunk partials -> context; normalize raw
// scores (already in d_out weights region) -> weights.
// grid (B, 9): y==8 -> context block; y<8 -> weights slice of 512.
// ============================================================
__global__ void __launch_bounds__(256) finalize_kernel(float* __restrict__ out)
{
    const int b = blockIdx.x, part = blockIdx.y, tid = threadIdx.x;

    float M = g_part_m[b * NCHUNK];
    #pragma unroll
    for (int c = 1; c < NCHUNK; c++) M = fmaxf(M, g_part_m[b * NCHUNK + c]);
    float L = 0.f;
    #pragma unroll
    for (int c = 0; c < NCHUNK; c++)
        L += __expf(g_part_m[b * NCHUNK + c] - M) * g_part_l[b * NCHUNK + c];
    const float invL = 1.f / L;

    if (part == 8) {
        // context [B,1,H] at out[0 .. B*H)
        float4 ctx = make_float4(0.f, 0.f, 0.f, 0.f);
        #pragma unroll 4
        for (int c = 0; c < NCHUNK; c++) {
            const float ew = __expf(g_part_m[b * NCHUNK + c] - M);
            float4 v = ((const float4*)(g_part_acc + (size_t)(b * NCHUNK + c) * HH))[tid];
            ctx.x += ew * v.x; ctx.y += ew * v.y;
            ctx.z += ew * v.z; ctx.w += ew * v.w;
        }
        ctx.x *= invL; ctx.y *= invL; ctx.z *= invL; ctx.w *= invL;
        ((float4*)(out + (size_t)b * HH))[tid] = ctx;
    } else {
        // weights [B,1,S]: normalize raw scores in place
        float* wout = out + (size_t)BB * HH + (size_t)b * SS + part * 512;
        #pragma unroll
        for (int s = tid; s < 512; s += 256)
            wout[s] = __expf(wout[s] - M) * invL;
    }
}

extern "C" void kernel_launch(void* const* d_in, const int* in_sizes, int n_in,
                              void* d_out, int out_size)
{
    const float* query = nullptr;
    const float* keys  = nullptr;
    const int*   mask  = nullptr;
    const float* W     = nullptr;
    for (int i = 0; i < n_in; i++) {
        switch (in_sizes[i]) {
            case BB * HH:        query = (const float*)d_in[i]; break;  // 32768
            case BB * SS * HH:   keys  = (const float*)d_in[i]; break;  // 134217728
            case BB * SS:        mask  = (const int*)d_in[i];   break;  // 131072
            case HH * HH:        W     = (const float*)d_in[i]; break;  // 1048576
            default: break;
        }
    }
    float* out = (float*)d_out;

    proj_kernel<<<HH / 8, 256>>>(query, W);
    flash_kernel<<<dim3(NCHUNK, BB), 256>>>(keys, mask, out + (size_t)BB * HH);
    finalize_kernel<<<dim3(BB, 9), 256>>>(out);
}

// round 4
// speedup vs baseline: 1.0435x; 1.0435x over previous
#include <cuda_runtime.h>
#include <math.h>

#define BB 32
#define SS 4096
#define HH 1024
#define NCHUNK 64
#define CHUNK (SS / NCHUNK)            // 64 rows per block
#define ROWS_PER_WARP (CHUNK / 8)      // 8 rows per warp
#define NEG_BIG -1.0e9f

// ---- scratch (no allocations allowed) ----
__device__ float g_q[BB * HH];                    // projected query
__device__ float g_part_m[BB * NCHUNK];           // per-chunk running max
__device__ float g_part_l[BB * NCHUNK];           // per-chunk exp-sum
__device__ float g_part_acc[BB * NCHUNK * HH];    // per-chunk unnormalized context (8MB)

// ============================================================
// Kernel A: q[b,o] = sum_h query[b,h] * W[o,h]
// grid (HH/4, 2) = 512 CTAs, 128 threads (4 warps).
// Warp-per-output-row o; 16 batches per warp as register
// partials p[16] -> 16 independent FMA chains (ILP) and 16
// pipelined shfl trees. W read 2x (8MB, 2nd pass L2-hot).
// ============================================================
__global__ void __launch_bounds__(128) proj_kernel(
    const float* __restrict__ query, const float* __restrict__ W)
{
    const int tid = threadIdx.x;
    const int w = tid >> 5, lane = tid & 31;
    const int o = blockIdx.x * 4 + w;
    const int b0 = blockIdx.y * 16;

    // W row: 32 floats/lane as 8 x float4 (kept in regs)
    const float4* wrow = (const float4*)(W + (size_t)o * HH);
    float4 wv[8];
    #pragma unroll
    for (int j = 0; j < 8; j++) wv[j] = wrow[j * 32 + lane];

    float p[16];
    #pragma unroll
    for (int bb = 0; bb < 16; bb++) {
        const float4* qq = (const float4*)(query + (size_t)(b0 + bb) * HH);
        float s = 0.f;
        #pragma unroll
        for (int j = 0; j < 8; j++) {
            float4 qv = __ldg(qq + j * 32 + lane);
            s += wv[j].x * qv.x + wv[j].y * qv.y + wv[j].z * qv.z + wv[j].w * qv.w;
        }
        p[bb] = s;
    }

    // 16 independent shfl reduction trees (pipeline across bb)
    #pragma unroll
    for (int off = 16; off > 0; off >>= 1) {
        #pragma unroll
        for (int bb = 0; bb < 16; bb++)
            p[bb] += __shfl_xor_sync(0xffffffffu, p[bb], off);
    }
    if (lane == 0) {
        #pragma unroll
        for (int bb = 0; bb < 16; bb++)
            g_q[(size_t)(b0 + bb) * HH + o] = p[bb];
    }
}

// ============================================================
// Kernel B: fused scores + online softmax + context partial.
// grid (NCHUNK, B) = 2048 CTAs, 256 threads (8 warps), warp-per-row.
// q lives in smem (frees 32 regs -> higher occupancy).
// Keys streamed with __ldcs (zero reuse; don't churn L2).
// [UNCHANGED from R3 — measured ~84us / 6.1 TB/s]
// ============================================================
__global__ void __launch_bounds__(256) flash_kernel(
    const float* __restrict__ keys,
    const int* __restrict__ mask,
    float* __restrict__ scores_out)
{
    const int chunk = blockIdx.x, b = blockIdx.y;
    const int tid = threadIdx.x, w = tid >> 5, lane = tid & 31;

    __shared__ float4 sq[HH / 4];          // 4KB projected query
    __shared__ float  s_m[8], s_l[8];
    __shared__ float4 s_acc[8][256];       // 32KB warp partial contexts

    {
        const float4* qsrc = (const float4*)(g_q + (size_t)b * HH);
        for (int i = tid; i < HH / 4; i += 256) sq[i] = qsrc[i];
    }
    __syncthreads();

    float4 acc[8];
    #pragma unroll
    for (int j = 0; j < 8; j++) acc[j] = make_float4(0.f, 0.f, 0.f, 0.f);
    float m = -INFINITY, l = 0.f;

    const int s0 = chunk * CHUNK + w * ROWS_PER_WARP;
    const int* mrow = mask + (size_t)b * SS;

    #pragma unroll 2
    for (int r = 0; r < ROWS_PER_WARP; r++) {
        const int s = s0 + r;
        const float4* kp = (const float4*)(keys + ((size_t)b * SS + s) * HH);

        float4 kv[8];
        float p = 0.f;
        #pragma unroll
        for (int j = 0; j < 8; j++) {
            kv[j] = __ldcs(kp + j * 32 + lane);
            float4 qv = sq[j * 32 + lane];
            p += kv[j].x * qv.x + kv[j].y * qv.y +
                 kv[j].z * qv.z + kv[j].w * qv.w;
        }
        #pragma unroll
        for (int off = 16; off > 0; off >>= 1)
            p += __shfl_xor_sync(0xffffffffu, p, off);

        const float score = (mrow[s] != 0) ? NEG_BIG : p;
        if (lane == 0) scores_out[(size_t)b * SS + s] = score;

        // online softmax update; key row still in registers
        const float mn = fmaxf(m, score);
        const float c  = __expf(m - mn);      // exp(-inf)=0 on first iter
        const float e  = __expf(score - mn);
        l = l * c + e;
        #pragma unroll
        for (int j = 0; j < 8; j++) {
            acc[j].x = acc[j].x * c + e * kv[j].x;
            acc[j].y = acc[j].y * c + e * kv[j].y;
            acc[j].z = acc[j].z * c + e * kv[j].z;
            acc[j].w = acc[j].w * c + e * kv[j].w;
        }
        m = mn;
    }

    // ---- combine 8 warps within the block ----
    if (lane == 0) { s_m[w] = m; s_l[w] = l; }
    #pragma unroll
    for (int j = 0; j < 8; j++) s_acc[w][j * 32 + lane] = acc[j];
    __syncthreads();

    float M = s_m[0];
    #pragma unroll
    for (int i = 1; i < 8; i++) M = fmaxf(M, s_m[i]);
    float ew[8], L = 0.f;
    #pragma unroll
    for (int i = 0; i < 8; i++) { ew[i] = __expf(s_m[i] - M); L += ew[i] * s_l[i]; }

    float4 cacc = make_float4(0.f, 0.f, 0.f, 0.f);
    #pragma unroll
    for (int i = 0; i < 8; i++) {
        float4 v = s_acc[i][tid];
        cacc.x += ew[i] * v.x; cacc.y += ew[i] * v.y;
        cacc.z += ew[i] * v.z; cacc.w += ew[i] * v.w;
    }
    const int pidx = b * NCHUNK + chunk;
    ((float4*)(g_part_acc + (size_t)pidx * HH))[tid] = cacc;
    if (tid == 0) { g_part_m[pidx] = M; g_part_l[pidx] = L; }
}

// ============================================================
// Kernel C: combine chunk partials -> context; normalize raw
// scores (already in d_out weights region) -> weights.
// grid (B, 9): y==8 -> context block; y<8 -> weights slice of 512.
// ============================================================
__global__ void __launch_bounds__(256) finalize_kernel(float* __restrict__ out)
{
    const int b = blockIdx.x, part = blockIdx.y, tid = threadIdx.x;

    float M = g_part_m[b * NCHUNK];
    #pragma unroll
    for (int c = 1; c < NCHUNK; c++) M = fmaxf(M, g_part_m[b * NCHUNK + c]);
    float L = 0.f;
    #pragma unroll
    for (int c = 0; c < NCHUNK; c++)
        L += __expf(g_part_m[b * NCHUNK + c] - M) * g_part_l[b * NCHUNK + c];
    const float invL = 1.f / L;

    if (part == 8) {
        // context [B,1,H] at out[0 .. B*H)
        float4 ctx = make_float4(0.f, 0.f, 0.f, 0.f);
        #pragma unroll 4
        for (int c = 0; c < NCHUNK; c++) {
            const float ew = __expf(g_part_m[b * NCHUNK + c] - M);
            float4 v = ((const float4*)(g_part_acc + (size_t)(b * NCHUNK + c) * HH))[tid];
            ctx.x += ew * v.x; ctx.y += ew * v.y;
            ctx.z += ew * v.z; ctx.w += ew * v.w;
        }
        ctx.x *= invL; ctx.y *= invL; ctx.z *= invL; ctx.w *= invL;
        ((float4*)(out + (size_t)b * HH))[tid] = ctx;
    } else {
        // weights [B,1,S]: normalize raw scores in place
        float* wout = out + (size_t)BB * HH + (size_t)b * SS + part * 512;
        #pragma unroll
        for (int s = tid; s < 512; s += 256)
            wout[s] = __expf(wout[s] - M) * invL;
    }
}

extern "C" void kernel_launch(void* const* d_in, const int* in_sizes, int n_in,
                              void* d_out, int out_size)
{
    const float* query = nullptr;
    const float* keys  = nullptr;
    const int*   mask  = nullptr;
    const float* W     = nullptr;
    for (int i = 0; i < n_in; i++) {
        switch (in_sizes[i]) {
            case BB * HH:        query = (const float*)d_in[i]; break;  // 32768
            case BB * SS * HH:   keys  = (const float*)d_in[i]; break;  // 134217728
            case BB * SS:        mask  = (const int*)d_in[i];   break;  // 131072
            case HH * HH:        W     = (const float*)d_in[i]; break;  // 1048576
            default: break;
        }
    }
    float* out = (float*)d_out;

    proj_kernel<<<dim3(HH / 4, 2), 128>>>(query, W);
    flash_kernel<<<dim3(NCHUNK, BB), 256>>>(keys, mask, out + (size_t)BB * HH);
    finalize_kernel<<<dim3(BB, 9), 256>>>(out);
}

// round 5
// speedup vs baseline: 1.0778x; 1.0329x over previous
#include <cuda_runtime.h>
#include <math.h>

#define BB 32
#define SS 4096
#define HH 1024
#define NCHUNK 64
#define CHUNK (SS / NCHUNK)            // 64 rows per block
#define ROWS_PER_WARP (CHUNK / 8)      // 8 rows per warp
#define NEG_BIG -1.0e9f

// ---- scratch (no allocations allowed) ----
__device__ float g_q[BB * HH];                    // projected query
__device__ float g_part_m[BB * NCHUNK];           // per-chunk running max
__device__ float g_part_l[BB * NCHUNK];           // per-chunk exp-sum
__device__ float g_part_acc[BB * NCHUNK * HH];    // per-chunk unnormalized context (8MB)

// ============================================================
// Kernel A: q[b,o] = sum_h query[b,h] * W[o,h]
// grid (HH/4, 4) = 1024 CTAs, 128 threads (4 warps).
// Warp-per-output-row o; 8 batches per warp as register
// partials p[8]. Occupancy ~7 CTAs/SM (was grid-limited at
// 3.5). W read 4x = 16MB but passes 2-4 are L2-hot; proj is
// latency-bound, not traffic-bound.
// ============================================================
__global__ void __launch_bounds__(128) proj_kernel(
    const float* __restrict__ query, const float* __restrict__ W)
{
    const int tid = threadIdx.x;
    const int w = tid >> 5, lane = tid & 31;
    const int o = blockIdx.x * 4 + w;
    const int b0 = blockIdx.y * 8;

    // W row: 32 floats/lane as 8 x float4 (kept in regs)
    const float4* wrow = (const float4*)(W + (size_t)o * HH);
    float4 wv[8];
    #pragma unroll
    for (int j = 0; j < 8; j++) wv[j] = wrow[j * 32 + lane];

    float p[8];
    #pragma unroll
    for (int bb = 0; bb < 8; bb++) {
        const float4* qq = (const float4*)(query + (size_t)(b0 + bb) * HH);
        float s = 0.f;
        #pragma unroll
        for (int j = 0; j < 8; j++) {
            float4 qv = __ldg(qq + j * 32 + lane);
            s += wv[j].x * qv.x + wv[j].y * qv.y + wv[j].z * qv.z + wv[j].w * qv.w;
        }
        p[bb] = s;
    }

    // 8 independent shfl reduction trees (pipelined)
    #pragma unroll
    for (int off = 16; off > 0; off >>= 1) {
        #pragma unroll
        for (int bb = 0; bb < 8; bb++)
            p[bb] += __shfl_xor_sync(0xffffffffu, p[bb], off);
    }
    if (lane == 0) {
        #pragma unroll
        for (int bb = 0; bb < 8; bb++)
            g_q[(size_t)(b0 + bb) * HH + o] = p[bb];
    }
}

// ============================================================
// Kernel B: fused scores + online softmax + context partial.
// grid (NCHUNK, B) = 2048 CTAs, 256 threads (8 warps), warp-per-row.
// q lives in smem; keys streamed with __ldcs (zero reuse).
// [UNCHANGED — measured ~84-93us, ~6.1 TB/s on the keys stream]
// ============================================================
__global__ void __launch_bounds__(256) flash_kernel(
    const float* __restrict__ keys,
    const int* __restrict__ mask,
    float* __restrict__ scores_out)
{
    const int chunk = blockIdx.x, b = blockIdx.y;
    const int tid = threadIdx.x, w = tid >> 5, lane = tid & 31;

    __shared__ float4 sq[HH / 4];          // 4KB projected query
    __shared__ float  s_m[8], s_l[8];
    __shared__ float4 s_acc[8][256];       // 32KB warp partial contexts

    {
        const float4* qsrc = (const float4*)(g_q + (size_t)b * HH);
        for (int i = tid; i < HH / 4; i += 256) sq[i] = qsrc[i];
    }
    __syncthreads();

    float4 acc[8];
    #pragma unroll
    for (int j = 0; j < 8; j++) acc[j] = make_float4(0.f, 0.f, 0.f, 0.f);
    float m = -INFINITY, l = 0.f;

    const int s0 = chunk * CHUNK + w * ROWS_PER_WARP;
    const int* mrow = mask + (size_t)b * SS;

    #pragma unroll 2
    for (int r = 0; r < ROWS_PER_WARP; r++) {
        const int s = s0 + r;
        const float4* kp = (const float4*)(keys + ((size_t)b * SS + s) * HH);

        float4 kv[8];
        float p = 0.f;
        #pragma unroll
        for (int j = 0; j < 8; j++) {
            kv[j] = __ldcs(kp + j * 32 + lane);
            float4 qv = sq[j * 32 + lane];
            p += kv[j].x * qv.x + kv[j].y * qv.y +
                 kv[j].z * qv.z + kv[j].w * qv.w;
        }
        #pragma unroll
        for (int off = 16; off > 0; off >>= 1)
            p += __shfl_xor_sync(0xffffffffu, p, off);

        const float score = (mrow[s] != 0) ? NEG_BIG : p;
        if (lane == 0) scores_out[(size_t)b * SS + s] = score;

        // online softmax update; key row still in registers
        const float mn = fmaxf(m, score);
        const float c  = __expf(m - mn);      // exp(-inf)=0 on first iter
        const float e  = __expf(score - mn);
        l = l * c + e;
        #pragma unroll
        for (int j = 0; j < 8; j++) {
            acc[j].x = acc[j].x * c + e * kv[j].x;
            acc[j].y = acc[j].y * c + e * kv[j].y;
            acc[j].z = acc[j].z * c + e * kv[j].z;
            acc[j].w = acc[j].w * c + e * kv[j].w;
        }
        m = mn;
    }

    // ---- combine 8 warps within the block ----
    if (lane == 0) { s_m[w] = m; s_l[w] = l; }
    #pragma unroll
    for (int j = 0; j < 8; j++) s_acc[w][j * 32 + lane] = acc[j];
    __syncthreads();

    float M = s_m[0];
    #pragma unroll
    for (int i = 1; i < 8; i++) M = fmaxf(M, s_m[i]);
    float ew[8], L = 0.f;
    #pragma unroll
    for (int i = 0; i < 8; i++) { ew[i] = __expf(s_m[i] - M); L += ew[i] * s_l[i]; }

    float4 cacc = make_float4(0.f, 0.f, 0.f, 0.f);
    #pragma unroll
    for (int i = 0; i < 8; i++) {
        float4 v = s_acc[i][tid];
        cacc.x += ew[i] * v.x; cacc.y += ew[i] * v.y;
        cacc.z += ew[i] * v.z; cacc.w += ew[i] * v.w;
    }
    const int pidx = b * NCHUNK + chunk;
    ((float4*)(g_part_acc + (size_t)pidx * HH))[tid] = cacc;
    if (tid == 0) { g_part_m[pidx] = M; g_part_l[pidx] = L; }
}

// ============================================================
// Kernel C: combine chunk partials -> context; normalize raw
// scores (already in d_out weights region) -> weights.
// grid (B, 9): y==8 -> context block; y<8 -> weights slice of 512.
// ============================================================
__global__ void __launch_bounds__(256) finalize_kernel(float* __restrict__ out)
{
    const int b = blockIdx.x, part = blockIdx.y, tid = threadIdx.x;

    float M = g_part_m[b * NCHUNK];
    #pragma unroll
    for (int c = 1; c < NCHUNK; c++) M = fmaxf(M, g_part_m[b * NCHUNK + c]);
    float L = 0.f;
    #pragma unroll
    for (int c = 0; c < NCHUNK; c++)
        L += __expf(g_part_m[b * NCHUNK + c] - M) * g_part_l[b * NCHUNK + c];
    const float invL = 1.f / L;

    if (part == 8) {
        // context [B,1,H] at out[0 .. B*H)
        float4 ctx = make_float4(0.f, 0.f, 0.f, 0.f);
        #pragma unroll 4
        for (int c = 0; c < NCHUNK; c++) {
            const float ew = __expf(g_part_m[b * NCHUNK + c] - M);
            float4 v = ((const float4*)(g_part_acc + (size_t)(b * NCHUNK + c) * HH))[tid];
            ctx.x += ew * v.x; ctx.y += ew * v.y;
            ctx.z += ew * v.z; ctx.w += ew * v.w;
        }
        ctx.x *= invL; ctx.y *= invL; ctx.z *= invL; ctx.w *= invL;
        ((float4*)(out + (size_t)b * HH))[tid] = ctx;
    } else {
        // weights [B,1,S]: normalize raw scores in place
        float* wout = out + (size_t)BB * HH + (size_t)b * SS + part * 512;
        #pragma unroll
        for (int s = tid; s < 512; s += 256)
            wout[s] = __expf(wout[s] - M) * invL;
    }
}

extern "C" void kernel_launch(void* const* d_in, const int* in_sizes, int n_in,
                              void* d_out, int out_size)
{
    const float* query = nullptr;
    const float* keys  = nullptr;
    const int*   mask  = nullptr;
    const float* W     = nullptr;
    for (int i = 0; i < n_in; i++) {
        switch (in_sizes[i]) {
            case BB * HH:        query = (const float*)d_in[i]; break;  // 32768
            case BB * SS * HH:   keys  = (const float*)d_in[i]; break;  // 134217728
            case BB * SS:        mask  = (const int*)d_in[i];   break;  // 131072
            case HH * HH:        W     = (const float*)d_in[i]; break;  // 1048576
            default: break;
        }
    }
    float* out = (float*)d_out;

    proj_kernel<<<dim3(HH / 4, 4), 128>>>(query, W);
    flash_kernel<<<dim3(NCHUNK, BB), 256>>>(keys, mask, out + (size_t)BB * HH);
    finalize_kernel<<<dim3(BB, 9), 256>>>(out);
}